// round 1
// baseline (speedup 1.0000x reference)
#include <cuda_runtime.h>
#include <stdint.h>

#define BATCH 16
#define HH 512
#define WW 512
#define WPR 16                 // 32-bit words per row
#define WPI (HH*WPR)           // 8192 words per image
#define NPIX (BATCH*HH*WW)     // 4194304
#define NBLK_A (NPIX/256)      // 16384

// ---------------- scratch (no allocation allowed) ----------------
__device__ uint32_t g_pred[BATCH*WPI];
__device__ uint32_t g_true[BATCH*WPI];
__device__ uint32_t g_ps[BATCH*WPI];
__device__ uint32_t g_ts[BATCH*WPI];
__device__ float    g_part[NBLK_A*5];
__device__ float    g_cl[BATCH];

// ---------------- kernel A: binarize + dice/focal partials -------
__device__ __forceinline__ float softplus_f(float x){
    // log(1+exp(x)), stable
    float ax = fabsf(x);
    return fmaxf(x, 0.f) + log1pf(__expf(-ax));
}

__global__ __launch_bounds__(256) void kA(const float* __restrict__ logits,
                                          const int*   __restrict__ tr){
    int i   = blockIdx.x*256 + threadIdx.x;           // global pixel
    int b   = i >> 18;                                 // 512*512 = 2^18
    int rem = i & ((1<<18)-1);
    float l0 = logits[(size_t)(b*2+0)*(HH*WW) + rem];
    float l1 = logits[(size_t)(b*2+1)*(HH*WW) + rem];
    int   t  = tr[i];

    float d = l1 - l0;
    unsigned pm = __ballot_sync(0xffffffffu, d > 0.f);
    unsigned tm = __ballot_sync(0xffffffffu, t > 0);
    if ((threadIdx.x & 31) == 0){
        g_pred[i>>5] = pm;
        g_true[i>>5] = tm;
    }

    // per-pixel loss terms (C=2): p1 = sigmoid(d)
    float p1 = 1.f / (1.f + __expf(-d));
    float p0 = 1.f - p1;
    float sp_pos = softplus_f(d);     // -log p0
    float sp_neg = softplus_f(-d);    // -log p1
    float ce = (t > 0) ? sp_neg : sp_pos;
    float pt = (t > 0) ? p1 : p0;
    float om = 1.f - pt;
    float fo = 0.25f * om * om * ce;

    float vals[5];
    vals[0] = (t > 0) ? 0.f : p0;   // sum probs[0] where true==0
    vals[1] = (t > 0) ? p1 : 0.f;   // sum probs[1] where true==1
    vals[2] = p1;                    // sum probs[1]
    vals[3] = (t > 0) ? 1.f : 0.f;  // count(true==1)
    vals[4] = fo;                    // focal sum

    __shared__ float red[8*5];
    int lane = threadIdx.x & 31, wid = threadIdx.x >> 5;
    #pragma unroll
    for (int v = 0; v < 5; v++){
        float x = vals[v];
        #pragma unroll
        for (int o = 16; o; o >>= 1) x += __shfl_down_sync(0xffffffffu, x, o);
        if (lane == 0) red[wid*5 + v] = x;
    }
    __syncthreads();
    if (wid == 0 && lane < 5){
        float s = 0.f;
        #pragma unroll
        for (int w = 0; w < 8; w++) s += red[w*5 + lane];
        g_part[(size_t)blockIdx.x*5 + lane] = s;
    }
}

// ---------------- kernel B: bit-parallel Zhang-Suen thinning -----
__device__ __forceinline__ uint32_t ldw(const uint32_t* S, int r, int w){
    return (r >= 0 && r < HH && w >= 0 && w < WPR) ? S[r*WPR + w] : 0u;
}

template<int SUB>
__device__ __forceinline__ void thin_pass(uint32_t* S, int tid, int* flag){
    uint32_t nv[8];
    bool any = false;
    #pragma unroll
    for (int k = 0; k < 8; k++){
        int idx = tid + k*1024;
        int r = idx >> 4, w = idx & 15;
        uint32_t cC = S[idx];
        uint32_t cL = ldw(S, r,   w-1), cR = ldw(S, r,   w+1);
        uint32_t nC = ldw(S, r-1, w),   nL = ldw(S, r-1, w-1), nR = ldw(S, r-1, w+1);
        uint32_t sC = ldw(S, r+1, w),   sL = ldw(S, r+1, w-1), sR = ldw(S, r+1, w+1);

        // neighbor masks: bit j = neighbor of pixel (r, w*32+j)
        uint32_t p2 = nC;                         // N
        uint32_t p6 = sC;                         // S
        uint32_t p4 = (cC >> 1) | (cR << 31);     // E
        uint32_t p8 = (cC << 1) | (cL >> 31);     // W
        uint32_t p3 = (nC >> 1) | (nR << 31);     // NE
        uint32_t p9 = (nC << 1) | (nL >> 31);     // NW
        uint32_t p5 = (sC >> 1) | (sR << 31);     // SE
        uint32_t p7 = (sC << 1) | (sL >> 31);     // SW

        // B = sum of 8 neighbor bits, bit-sliced carry-save adders
        uint32_t sa = p2 ^ p3 ^ p4, ca = (p2 & p3) | (p4 & (p2 ^ p3));
        uint32_t sb = p5 ^ p6 ^ p7, cb = (p5 & p6) | (p7 & (p5 ^ p6));
        uint32_t sc = p8 ^ p9,      cc = p8 & p9;
        uint32_t S0 = sa ^ sb ^ sc, cd = (sa & sb) | (sc & (sa ^ sb));
        uint32_t t1v = ca ^ cb ^ cc, c1a = (ca & cb) | (cc & (ca ^ cb));
        uint32_t S1 = t1v ^ cd,      c1b = t1v & cd;
        uint32_t S2 = c1a ^ c1b,     S3 = c1a & c1b;
        // 2 <= B <= 6
        uint32_t cond1 = (S1 | S2 | S3) & ~(S3 | (S2 & S1 & S0));

        // A == 1: exactly one 0->1 transition in cyclic p2..p9
        uint32_t t0 = ~p2 & p3;
        uint32_t t1_ = ~p3 & p4;
        uint32_t t2 = ~p4 & p5;
        uint32_t t3 = ~p5 & p6;
        uint32_t t4 = ~p6 & p7;
        uint32_t t5 = ~p7 & p8;
        uint32_t t6 = ~p8 & p9;
        uint32_t t7 = ~p9 & p2;
        uint32_t onep = t0, two = 0;
        two |= onep & t1_; onep |= t1_;
        two |= onep & t2;  onep |= t2;
        two |= onep & t3;  onep |= t3;
        two |= onep & t4;  onep |= t4;
        two |= onep & t5;  onep |= t5;
        two |= onep & t6;  onep |= t6;
        two |= onep & t7;  onep |= t7;
        uint32_t condA = onep & ~two;

        uint32_t c3m, c4m;
        if (SUB == 0){ c3m = ~(p2 & p4 & p6); c4m = ~(p4 & p6 & p8); }
        else         { c3m = ~(p2 & p4 & p8); c4m = ~(p2 & p6 & p8); }

        uint32_t remv = cC & cond1 & condA & c3m & c4m;
        nv[k] = cC & ~remv;
        any = any || (remv != 0u);
    }
    __syncthreads();   // all reads done before any write
    #pragma unroll
    for (int k = 0; k < 8; k++) S[tid + k*1024] = nv[k];
    if (any) *flag = 1;
    __syncthreads();   // writes + flag visible
}

__global__ __launch_bounds__(1024) void kB(){
    __shared__ uint32_t S[WPI];
    __shared__ int sh_changed;
    int img = blockIdx.x >> 1;
    const uint32_t* src = (blockIdx.x & 1) ? (g_true + img*WPI) : (g_pred + img*WPI);
    uint32_t*       dst = (blockIdx.x & 1) ? (g_ts   + img*WPI) : (g_ps   + img*WPI);
    int tid = threadIdx.x;
    #pragma unroll
    for (int k = 0; k < 8; k++) S[tid + k*1024] = src[tid + k*1024];
    __syncthreads();
    for (;;){
        if (tid == 0) sh_changed = 0;
        // reset happens-before any set: sets occur after thin_pass's internal sync
        thin_pass<0>(S, tid, &sh_changed);
        thin_pass<1>(S, tid, &sh_changed);
        int ch = sh_changed;   // thin_pass ends with __syncthreads => visible
        __syncthreads();       // everyone has read before next reset
        if (!ch) break;
    }
    #pragma unroll
    for (int k = 0; k < 8; k++) dst[tid + k*1024] = S[tid + k*1024];
}

// ---------------- kernel C: per-image clDice ---------------------
__global__ __launch_bounds__(256) void kC(){
    int b = blockIdx.x, tid = threadIdx.x;
    int inter = 0, sp = 0, st = 0;
    for (int k = tid; k < WPI; k += 256){
        uint32_t a = g_ps[b*WPI + k], c = g_ts[b*WPI + k];
        inter += __popc(a & c);
        sp    += __popc(a);
        st    += __popc(c);
    }
    __shared__ int red[8*3];
    int lane = tid & 31, wid = tid >> 5;
    int v3[3] = {inter, sp, st};
    #pragma unroll
    for (int v = 0; v < 3; v++){
        int x = v3[v];
        #pragma unroll
        for (int o = 16; o; o >>= 1) x += __shfl_down_sync(0xffffffffu, x, o);
        if (lane == 0) red[wid*3 + v] = x;
    }
    __syncthreads();
    if (tid == 0){
        int ti = 0, tp = 0, tt = 0;
        #pragma unroll
        for (int w = 0; w < 8; w++){ ti += red[w*3]; tp += red[w*3+1]; tt += red[w*3+2]; }
        g_cl[b] = (2.f*(float)ti + 1e-6f) / ((float)(tp + tt) + 1e-6f);
    }
}

// ---------------- kernel D: final scalar combine -----------------
__global__ __launch_bounds__(256) void kD(float* __restrict__ out){
    __shared__ float sh[256];
    int tid = threadIdx.x;
    float acc[5] = {0.f, 0.f, 0.f, 0.f, 0.f};
    for (int k = tid; k < NBLK_A; k += 256){
        #pragma unroll
        for (int v = 0; v < 5; v++) acc[v] += g_part[(size_t)k*5 + v];
    }
    float tot[5];
    #pragma unroll
    for (int v = 0; v < 5; v++){
        sh[tid] = acc[v];
        __syncthreads();
        for (int s = 128; s; s >>= 1){
            if (tid < s) sh[tid] += sh[tid + s];
            __syncthreads();
        }
        tot[v] = sh[0];
        __syncthreads();
    }
    if (tid == 0){
        const float EPS = 1e-6f;
        float TOT = (float)NPIX;
        float s_i0 = tot[0], s_i1 = tot[1], s_p1 = tot[2], n1 = tot[3], sf = tot[4];
        float card0 = (TOT - s_p1) + (TOT - n1);
        float card1 = s_p1 + n1;
        float dice = 1.f - 0.5f * ((2.f*s_i0 + EPS)/(card0 + EPS)
                                 + (2.f*s_i1 + EPS)/(card1 + EPS));
        float cls = 0.f;
        for (int b = 0; b < BATCH; b++) cls += g_cl[b];
        float cl = 1.f - cls / (float)BATCH;
        float focal = sf / TOT;
        out[0] = 0.7f*cl + 0.1f*dice + 0.2f*focal;
    }
}

// ---------------- launch -----------------------------------------
extern "C" void kernel_launch(void* const* d_in, const int* in_sizes, int n_in,
                              void* d_out, int out_size){
    const float* logits = (const float*)d_in[0];
    const int*   tr     = (const int*)d_in[1];
    kA<<<NBLK_A, 256>>>(logits, tr);
    kB<<<2*BATCH, 1024>>>();
    kC<<<BATCH, 256>>>();
    kD<<<1, 256>>>((float*)d_out);
}

// round 2
// speedup vs baseline: 2.1420x; 2.1420x over previous
#include <cuda_runtime.h>
#include <stdint.h>
#include <cooperative_groups.h>
namespace cg = cooperative_groups;

#define BATCH 16
#define HH 512
#define WW 512
#define WPR 16                  // 32-bit words per row
#define WPI (HH*WPR)            // 8192 words per image
#define NPIX (BATCH*HH*WW)      // 4194304
#define NBLK 2048               // kA blocks (8 px/thread, 256 thr)
#define ROWS_CTA 128            // rows per cluster CTA
#define SSTRIDE 18              // padded row stride (bank-conflict-free)
#define SBUF (ROWS_CTA*SSTRIDE) // 2304 words per buffer

// ---------------- scratch (no allocation allowed) ----------------
__device__ uint32_t g_pred[BATCH*WPI];
__device__ uint32_t g_true[BATCH*WPI];
__device__ uint32_t g_ps[BATCH*WPI];
__device__ uint32_t g_ts[BATCH*WPI];
__device__ float    g_part[5*NBLK];
__device__ float    g_cl[BATCH];

// ---------------- kernel A: binarize + dice/focal partials -------
__global__ __launch_bounds__(256) void kA(const float* __restrict__ logits,
                                          const int*   __restrict__ tr){
    int tid = threadIdx.x;
    int gt  = blockIdx.x*256 + tid;
    int i8  = gt*8;                       // base pixel
    int b   = i8 >> 18;
    int rem = i8 & ((1<<18)-1);

    const float4* P0 = (const float4*)logits;
    size_t i0 = (((size_t)(2*b)   << 18) + rem) >> 2;
    size_t i1 = (((size_t)(2*b+1) << 18) + rem) >> 2;
    float4 a0 = P0[i0],   a1 = P0[i0+1];
    float4 b0 = P0[i1],   b1 = P0[i1+1];
    const int4* T = (const int4*)tr;
    int4 t0 = T[i8>>2], t1 = T[(i8>>2)+1];

    float L0[8] = {a0.x,a0.y,a0.z,a0.w,a1.x,a1.y,a1.z,a1.w};
    float L1[8] = {b0.x,b0.y,b0.z,b0.w,b1.x,b1.y,b1.z,b1.w};
    int   TT[8] = {t0.x,t0.y,t0.z,t0.w,t1.x,t1.y,t1.z,t1.w};

    unsigned pm = 0, tm = 0;
    float s0=0.f, s1=0.f, s2=0.f, s3=0.f, s4=0.f;
    #pragma unroll
    for (int j = 0; j < 8; j++){
        float d = L1[j] - L0[j];
        bool pd = d > 0.f;
        bool tp = TT[j] > 0;
        pm |= (unsigned)pd << j;
        tm |= (unsigned)tp << j;
        float ad = fabsf(d);
        float e  = __expf(-ad);
        float pb = __fdividef(1.f, 1.f + e);   // sigmoid(|d|)
        float ps = 1.f - pb;                    // sigmoid(-|d|)
        float lg = -__logf(pb);                 // log(1+e)
        float p1 = pd ? pb : ps;
        float p0 = 1.f - p1;
        float ce = (tp == pd) ? lg : (ad + lg);
        float pt = tp ? p1 : p0;
        float om = 1.f - pt;
        s4 += 0.25f * om * om * ce;
        s2 += p1;
        if (tp){ s1 += p1; s3 += 1.f; }
        else   { s0 += p0; }
    }
    ((uint8_t*)g_pred)[gt] = (uint8_t)pm;
    ((uint8_t*)g_true)[gt] = (uint8_t)tm;

    __shared__ float red[8*5];
    int lane = tid & 31, wid = tid >> 5;
    float vals[5] = {s0, s1, s2, s3, s4};
    #pragma unroll
    for (int v = 0; v < 5; v++){
        float x = vals[v];
        #pragma unroll
        for (int o = 16; o; o >>= 1) x += __shfl_down_sync(0xffffffffu, x, o);
        if (lane == 0) red[wid*5 + v] = x;
    }
    __syncthreads();
    if (wid == 0 && lane < 5){
        float s = 0.f;
        #pragma unroll
        for (int w = 0; w < 8; w++) s += red[w*5 + lane];
        g_part[lane*NBLK + blockIdx.x] = s;
    }
}

// ---------------- kernel B: clustered bit-parallel Zhang-Suen ----
template<int SUB>
__device__ __forceinline__ bool thin4(const uint32_t* __restrict__ src,
                                      uint32_t* __restrict__ dst,
                                      const uint32_t* up, const uint32_t* dn,
                                      int g, int w){
    uint32_t C[6], E[6], Wm[6];
    #pragma unroll
    for (int i = 0; i < 6; i++){
        int r = 4*g - 1 + i;
        uint32_t c, l, rr;
        if (r >= 0 && r <= ROWS_CTA-1){
            int base = r*SSTRIDE;
            c  = src[base + w];
            l  = (w > 0)  ? src[base + w - 1] : 0u;
            rr = (w < 15) ? src[base + w + 1] : 0u;
        } else if (r < 0){
            if (up){
                int base = (ROWS_CTA-1)*SSTRIDE;
                c  = up[base + w];
                l  = (w > 0)  ? up[base + w - 1] : 0u;
                rr = (w < 15) ? up[base + w + 1] : 0u;
            } else { c = l = rr = 0u; }
        } else {
            if (dn){
                c  = dn[w];
                l  = (w > 0)  ? dn[w - 1] : 0u;
                rr = (w < 15) ? dn[w + 1] : 0u;
            } else { c = l = rr = 0u; }
        }
        C[i]  = c;
        E[i]  = __funnelshift_r(c, rr, 1);   // east  neighbors
        Wm[i] = __funnelshift_l(l, c, 1);    // west  neighbors
    }
    bool any = false;
    #pragma unroll
    for (int k = 0; k < 4; k++){
        int i = k + 1;
        uint32_t cC = C[i];
        uint32_t p2 = C[i-1], p3 = E[i-1], p9 = Wm[i-1];
        uint32_t p4 = E[i],   p8 = Wm[i];
        uint32_t p6 = C[i+1], p5 = E[i+1], p7 = Wm[i+1];

        // B in [2,6], bit-sliced CSA
        uint32_t sa = p2 ^ p3 ^ p4, ca = (p2 & p3) | (p4 & (p2 ^ p3));
        uint32_t sb = p5 ^ p6 ^ p7, cb = (p5 & p6) | (p7 & (p5 ^ p6));
        uint32_t sc = p8 ^ p9,      cc = p8 & p9;
        uint32_t S0 = sa ^ sb ^ sc, cd = (sa & sb) | (sc & (sa ^ sb));
        uint32_t t1v = ca ^ cb ^ cc, c1a = (ca & cb) | (cc & (ca ^ cb));
        uint32_t S1 = t1v ^ cd,      c1b = t1v & cd;
        uint32_t S2 = c1a ^ c1b,     S3 = c1a & c1b;
        uint32_t cond1 = (S1 | S2 | S3) & ~(S3 | (S2 & S1 & S0));

        // A == 1
        uint32_t t0 = ~p2 & p3;
        uint32_t t1_ = ~p3 & p4;
        uint32_t t2 = ~p4 & p5;
        uint32_t t3 = ~p5 & p6;
        uint32_t t4 = ~p6 & p7;
        uint32_t t5 = ~p7 & p8;
        uint32_t t6 = ~p8 & p9;
        uint32_t t7 = ~p9 & p2;
        uint32_t onep = t0, two = 0;
        two |= onep & t1_; onep |= t1_;
        two |= onep & t2;  onep |= t2;
        two |= onep & t3;  onep |= t3;
        two |= onep & t4;  onep |= t4;
        two |= onep & t5;  onep |= t5;
        two |= onep & t6;  onep |= t6;
        two |= onep & t7;  onep |= t7;
        uint32_t condA = onep & ~two;

        uint32_t c3m, c4m;
        if (SUB == 0){ c3m = ~(p2 & p4 & p6); c4m = ~(p4 & p6 & p8); }
        else         { c3m = ~(p2 & p4 & p8); c4m = ~(p2 & p6 & p8); }

        uint32_t remv = cC & cond1 & condA & c3m & c4m;
        dst[(4*g + k)*SSTRIDE + w] = cC & ~remv;
        any = any || (remv != 0u);
    }
    return any;
}

__global__ void __cluster_dims__(4,1,1) __launch_bounds__(512) kB(){
    __shared__ uint32_t S[2][SBUF];
    __shared__ int s_flag;
    __shared__ int s_any;

    cg::cluster_group cl = cg::this_cluster();
    unsigned rank = cl.block_rank();             // 0..3
    int unit = blockIdx.x >> 2;                  // 0..31
    int img  = unit >> 1;
    int sel  = unit & 1;

    const uint32_t* srcg = (sel ? g_true : g_pred) + img*WPI + rank*2048;
    uint32_t*       dstg = (sel ? g_ts   : g_ps)   + img*WPI + rank*2048;

    int tid = threadIdx.x;
    // load with stride-18 layout
    #pragma unroll
    for (int it = 0; it < 4; it++){
        int idx = tid + it*512;
        int r = idx >> 4, w = idx & 15;
        S[0][r*SSTRIDE + w] = srcg[idx];
    }

    uint32_t* upB = (rank > 0) ? cl.map_shared_rank(&S[0][0], rank-1) : (uint32_t*)0;
    uint32_t* dnB = (rank < 3) ? cl.map_shared_rank(&S[0][0], rank+1) : (uint32_t*)0;
    int* flag_peer[4];
    #pragma unroll
    for (int r = 0; r < 4; r++) flag_peer[r] = cl.map_shared_rank(&s_flag, r);

    int g = tid >> 4, w = tid & 15;

    for (;;){
        cl.sync();                       // all loads/prev-iter flag reads done
        if (tid == 0) s_flag = 0;
        __syncthreads();

        bool a0 = thin4<0>(&S[0][0], &S[1][0],
                           upB ? upB + 0    : (uint32_t*)0,
                           dnB ? dnB + 0    : (uint32_t*)0, g, w);
        if (a0) s_flag = 1;
        cl.sync();                       // buffer1 complete cluster-wide

        bool a1 = thin4<1>(&S[1][0], &S[0][0],
                           upB ? upB + SBUF : (uint32_t*)0,
                           dnB ? dnB + SBUF : (uint32_t*)0, g, w);
        if (a1) s_flag = 1;
        cl.sync();                       // buffer0 complete, flags final

        if (tid == 0){
            int any = 0;
            #pragma unroll
            for (int r = 0; r < 4; r++) any |= *flag_peer[r];
            s_any = any;
        }
        __syncthreads();
        if (!s_any) break;
    }

    #pragma unroll
    for (int it = 0; it < 4; it++){
        int idx = tid + it*512;
        int r = idx >> 4, wq = idx & 15;
        dstg[idx] = S[0][r*SSTRIDE + wq];
    }
    cl.sync();    // no CTA exits while peers may still read its smem
}

// ---------------- kernel C: per-image clDice ---------------------
__global__ __launch_bounds__(256) void kC(){
    int b = blockIdx.x, tid = threadIdx.x;
    int inter = 0, sp = 0, st = 0;
    const uint4* A = (const uint4*)(g_ps + b*WPI);
    const uint4* Cc = (const uint4*)(g_ts + b*WPI);
    for (int k = tid; k < WPI/4; k += 256){
        uint4 a = A[k], c = Cc[k];
        inter += __popc(a.x & c.x) + __popc(a.y & c.y) + __popc(a.z & c.z) + __popc(a.w & c.w);
        sp    += __popc(a.x) + __popc(a.y) + __popc(a.z) + __popc(a.w);
        st    += __popc(c.x) + __popc(c.y) + __popc(c.z) + __popc(c.w);
    }
    __shared__ int red[8*3];
    int lane = tid & 31, wid = tid >> 5;
    int v3[3] = {inter, sp, st};
    #pragma unroll
    for (int v = 0; v < 3; v++){
        int x = v3[v];
        #pragma unroll
        for (int o = 16; o; o >>= 1) x += __shfl_down_sync(0xffffffffu, x, o);
        if (lane == 0) red[wid*3 + v] = x;
    }
    __syncthreads();
    if (tid == 0){
        int ti = 0, tp = 0, tt = 0;
        #pragma unroll
        for (int w = 0; w < 8; w++){ ti += red[w*3]; tp += red[w*3+1]; tt += red[w*3+2]; }
        g_cl[b] = (2.f*(float)ti + 1e-6f) / ((float)(tp + tt) + 1e-6f);
    }
}

// ---------------- kernel D: final scalar combine -----------------
__global__ __launch_bounds__(256) void kD(float* __restrict__ out){
    int tid = threadIdx.x;
    __shared__ float red[8*5];
    int lane = tid & 31, wid = tid >> 5;
    #pragma unroll
    for (int v = 0; v < 5; v++){
        const float4* P = (const float4*)(g_part + v*NBLK);
        float4 a = P[tid*2], b = P[tid*2+1];
        float x = ((a.x + a.y) + (a.z + a.w)) + ((b.x + b.y) + (b.z + b.w));
        #pragma unroll
        for (int o = 16; o; o >>= 1) x += __shfl_down_sync(0xffffffffu, x, o);
        if (lane == 0) red[wid*5 + v] = x;
    }
    __syncthreads();
    if (tid == 0){
        float tot[5];
        #pragma unroll
        for (int v = 0; v < 5; v++){
            float s = 0.f;
            #pragma unroll
            for (int w = 0; w < 8; w++) s += red[w*5 + v];
            tot[v] = s;
        }
        const float EPS = 1e-6f;
        float TOT = (float)NPIX;
        float s_i0 = tot[0], s_i1 = tot[1], s_p1 = tot[2], n1 = tot[3], sf = tot[4];
        float card0 = (TOT - s_p1) + (TOT - n1);
        float card1 = s_p1 + n1;
        float dice = 1.f - 0.5f * ((2.f*s_i0 + EPS)/(card0 + EPS)
                                 + (2.f*s_i1 + EPS)/(card1 + EPS));
        float cls = 0.f;
        for (int b = 0; b < BATCH; b++) cls += g_cl[b];
        float cl = 1.f - cls / (float)BATCH;
        float focal = sf / TOT;
        out[0] = 0.7f*cl + 0.1f*dice + 0.2f*focal;
    }
}

// ---------------- launch -----------------------------------------
extern "C" void kernel_launch(void* const* d_in, const int* in_sizes, int n_in,
                              void* d_out, int out_size){
    const float* logits = (const float*)d_in[0];
    const int*   tr     = (const int*)d_in[1];
    kA<<<NBLK, 256>>>(logits, tr);
    kB<<<8*BATCH, 512>>>();
    kC<<<BATCH, 256>>>();
    kD<<<1, 256>>>((float*)d_out);
}